// round 12
// baseline (speedup 1.0000x reference)
#include <cuda_runtime.h>
#include <cstdint>

// path_generator_GAD  (N=131072 paths, T=251)
// s' = s + (b0+b1*s)*dt + (a0+a1*max(s,0))^g * Z*sqrt(dt)
//
// R12 = R11 + EARLY BUFFER RELEASE: consumer loads its tile into registers,
// arrives on the empty barrier immediately (arrive = .release, orders the
// LDS), and computes/writes back while the producer refills the same stage.
// Outputs staged in a separate OBUF (stride 20, 16B-aligned STS.128).
// Everything else identical to R11 (TW=16/RW=20/3 stages/dual producers/
// persistent 148 CTAs).

#define TSTEPS  251
#define DT_F    0.004f
#define SQRT_DT 0.063245553203367586f
#define S0_F    100.0f
#define TW      16
#define RW      20                  // floats per row slot (16B multiple)
#define CHUNKS  5                   // RW/4 16B chunks per row
#define NROWS   128
#define NTILES  16                  // ceil(250/16)
#define STAGES  3
#define PLANES  64                  // producer lanes (2 warps)
#define ARRF    (NROWS * RW)        // 2560 floats per array tile
#define BUFF    (6 * ARRF)          // 15360 floats per stage
#define DATA_OFF 64                 // floats reserved for barriers
#define OBS     20                  // OBUF slot stride (floats, 16B-aligned)
#define OBUF_OFF (DATA_OFF + STAGES * BUFF)

__device__ __forceinline__ void cp16(unsigned sa, const float* g) {
    asm volatile("cp.async.cg.shared.global [%0], [%1], 16;" :: "r"(sa), "l"(g));
}
__device__ __forceinline__ void cp4(unsigned sa, const float* g) {
    asm volatile("cp.async.ca.shared.global [%0], [%1], 4;" :: "r"(sa), "l"(g));
}
__device__ __forceinline__ void mbar_init(unsigned a, unsigned cnt) {
    asm volatile("mbarrier.init.shared.b64 [%0], %1;" :: "r"(a), "r"(cnt));
}
__device__ __forceinline__ void mbar_arrive(unsigned a) {
    asm volatile("mbarrier.arrive.release.cta.shared::cta.b64 _, [%0];" :: "r"(a) : "memory");
}
__device__ __forceinline__ void cp_arrive_noinc(unsigned a) {
    asm volatile("cp.async.mbarrier.arrive.noinc.shared.b64 [%0];" :: "r"(a) : "memory");
}
__device__ __forceinline__ void mbar_wait(unsigned a, unsigned ph) {
    unsigned done;
    asm volatile(
        "{\n\t.reg .pred p;\n\t"
        "mbarrier.try_wait.parity.acquire.cta.shared::cta.b64 p, [%1], %2;\n\t"
        "selp.b32 %0,1,0,p;\n\t}"
        : "=r"(done) : "r"(a), "r"(ph) : "memory");
    while (!done) {
        asm volatile(
            "{\n\t.reg .pred p;\n\t"
            "mbarrier.try_wait.parity.acquire.cta.shared::cta.b64 p, [%1], %2, 0x989680;\n\t"
            "selp.b32 %0,1,0,p;\n\t}"
            : "=r"(done) : "r"(a), "r"(ph) : "memory");
    }
}

template<int E>
__device__ __forceinline__ float elemf(const float4 (&v)[CHUNKS]) {
    constexpr int c = E >> 2;
    constexpr int m = E & 3;
    if constexpr (m == 0) return v[c].x;
    else if constexpr (m == 1) return v[c].y;
    else if constexpr (m == 2) return v[c].z;
    else return v[c].w;
}

template<int S>
__device__ __forceinline__ float run16(float s,
    const float4 (&vz)[CHUNKS], const float4 (&va0)[CHUNKS],
    const float4 (&va1)[CHUNKS], const float4 (&vb0)[CHUNKS],
    const float4 (&vb1)[CHUNKS], const float4 (&vg)[CHUNKS],
    float (&o)[TW])
{
#define ONE(J)                                                         \
    {                                                                  \
        float a0 = fmaf(elemf<S+J>(va0), 0.10f, 0.05f);                \
        float a1 = fmaf(elemf<S+J>(va1), 0.20f, 0.10f);                \
        float b0 = elemf<S+J>(vb0) * 0.05f;                            \
        float b1 = elemf<S+J>(vb1) * 0.10f;                            \
        float g  = fmaf(elemf<S+J>(vg), 0.20f, 0.80f);                 \
        float zt = elemf<S+J>(vz) * SQRT_DT;                           \
        float base = fmaf(a1, fmaxf(s, 0.0f), a0);                     \
        s = fmaf(fmaf(b1, s, b0), DT_F, s) + __powf(base, g) * zt;     \
        o[J] = s;                                                      \
    }
    ONE(0)  ONE(1)  ONE(2)  ONE(3)  ONE(4)  ONE(5)  ONE(6)  ONE(7)
    ONE(8)  ONE(9)  ONE(10) ONE(11) ONE(12) ONE(13) ONE(14) ONE(15)
#undef ONE
    return s;
}

__global__ void __launch_bounds__(192, 1)
gad_kernel(const float* __restrict__ Z,
           const float* __restrict__ Ua0,
           const float* __restrict__ Ua1,
           const float* __restrict__ Ub0,
           const float* __restrict__ Ub1,
           const float* __restrict__ Ug,
           float* __restrict__ out, int ngroups)
{
    extern __shared__ float smem[];
    const int tid = threadIdx.x;
    const unsigned sb = (unsigned)__cvta_generic_to_shared(smem);
    if (tid == 0) {
        #pragma unroll
        for (int s = 0; s < STAGES; ++s) {
            mbar_init(sb + s * 16,     PLANES);  // full: 64 producer lanes
            mbar_init(sb + s * 16 + 8, 128);     // empty: 128 consumer threads
        }
    }
    __syncthreads();

    float* data = smem + DATA_OFF;
    float* obuf = smem + OBUF_OFF;
    const unsigned dbase = sb + DATA_OFF * 4u;

    if (tid >= 128) {
        // ============ producer warps (2), persistent across groups ============
        const int lane = tid - 128;              // 0..63
        int ps = 0, pph = 1;
        for (int g = blockIdx.x; g < ngroups; g += gridDim.x) {
            const int pB = g * NROWS;
            for (int k = 0; k < NTILES; ++k) {
                const unsigned ful = sb + ps * 16;
                const unsigned emp = ful + 8;
                mbar_wait(emp, pph);
                const unsigned stage = dbase + (unsigned)(ps * BUFF) * 4u;
                const int t0 = 1 + k * TW;
                if (k < NTILES - 1) {
                    #pragma unroll
                    for (int i = 0; i < 10; ++i) {
                        const int c    = lane + PLANES * i;  // 0..639
                        const int row  = c / CHUNKS;
                        const int kk   = c - row * CHUNKS;   // 0..4
                        const int slot = ((row & 3) << 5) | (row >> 2);
                        const int slack = (t0 - row) & 3;
                        const int gi = (pB + row) * TSTEPS + t0 - slack + kk * 4;
                        const unsigned d = stage + (unsigned)(slot * RW + kk * 4) * 4u;
                        cp16(d + 0u * (ARRF * 4), Z   + gi);
                        cp16(d + 1u * (ARRF * 4), Ua0 + gi);
                        cp16(d + 2u * (ARRF * 4), Ua1 + gi);
                        cp16(d + 3u * (ARRF * 4), Ub0 + gi);
                        cp16(d + 4u * (ARRF * 4), Ub1 + gi);
                        cp16(d + 5u * (ARRF * 4), Ug  + gi);
                    }
                } else {
                    // last tile (w=10): exact 4B copies (no tail over-read)
                    const int w = TSTEPS - t0;               // 10
                    for (int idx = lane; idx < NROWS * w; idx += PLANES) {
                        const int row  = idx / w;
                        const int j    = idx - row * w;
                        const int slot = ((row & 3) << 5) | (row >> 2);
                        const int slack = (t0 - row) & 3;
                        const int gi = (pB + row) * TSTEPS + t0 + j;
                        const unsigned d = stage + (unsigned)(slot * RW + slack + j) * 4u;
                        cp4(d + 0u * (ARRF * 4), Z   + gi);
                        cp4(d + 1u * (ARRF * 4), Ua0 + gi);
                        cp4(d + 2u * (ARRF * 4), Ua1 + gi);
                        cp4(d + 3u * (ARRF * 4), Ub0 + gi);
                        cp4(d + 4u * (ARRF * 4), Ub1 + gi);
                        cp4(d + 5u * (ARRF * 4), Ug  + gi);
                    }
                }
                cp_arrive_noinc(ful);
                if (++ps == STAGES) { ps = 0; pph ^= 1; }
            }
        }
    } else {
        // ============ consumer warps (4), persistent across groups ============
        const int w32  = tid >> 5;          // warp id 0..3
        const int lane = tid & 31;
        const int r    = 4 * lane + w32;    // my path row (slack-uniform warps)
        const int slot = tid;               // smem slot (80B lane stride)
        const int col  = lane & 15;         // writeback role: 16 cols
        const int rg   = lane >> 4;         // 0/1
        int cs = 0, cph = 0;

        for (int g = blockIdx.x; g < ngroups; g += gridDim.x) {
            const int pB = g * NROWS;
            out[(pB + r) * TSTEPS] = S0_F;  // column 0 = S0
            float s = S0_F;

            for (int k = 0; k < NTILES; ++k) {
                const unsigned ful = sb + cs * 16;
                const unsigned emp = ful + 8;
                mbar_wait(ful, cph);

                float* B = data + cs * BUFF;
                const int t0 = 1 + k * TW;
                const int wv = min(TW, TSTEPS - t0);
                const int s4 = (t0 - w32) & 3;      // warp-uniform slack

                if (k < NTILES - 1) {
                    // ---- pull the whole tile into registers ----
                    float4 vz[CHUNKS], va0[CHUNKS], va1[CHUNKS],
                           vb0[CHUNKS], vb1[CHUNKS], vg[CHUNKS];
                    const float4* p = reinterpret_cast<const float4*>(B) + slot * CHUNKS;
                    const int A4 = ARRF / 4;        // 640 float4 per array
                    #pragma unroll
                    for (int c = 0; c < CHUNKS; ++c) {
                        vz[c]  = p[0 * A4 + c];
                        va0[c] = p[1 * A4 + c];
                        va1[c] = p[2 * A4 + c];
                        vb0[c] = p[3 * A4 + c];
                        vb1[c] = p[4 * A4 + c];
                        vg[c]  = p[5 * A4 + c];
                    }
                    // ---- EARLY RELEASE: stage is free; producer refills it
                    //      while we compute (arrive has .release -> orders LDS)
                    mbar_arrive(emp);

                    float o[TW];
                    switch (s4) {   // warp-uniform: exactly one case executes
                        case 0: s = run16<0>(s, vz, va0, va1, vb0, vb1, vg, o); break;
                        case 1: s = run16<1>(s, vz, va0, va1, vb0, vb1, vg, o); break;
                        case 2: s = run16<2>(s, vz, va0, va1, vb0, vb1, vg, o); break;
                        default: s = run16<3>(s, vz, va0, va1, vb0, vb1, vg, o); break;
                    }
                    // ---- stage outputs in OBUF (not the ring buffer) ----
                    float4* q = reinterpret_cast<float4*>(obuf + slot * OBS);
                    q[0] = make_float4(o[0],  o[1],  o[2],  o[3]);
                    q[1] = make_float4(o[4],  o[5],  o[6],  o[7]);
                    q[2] = make_float4(o[8],  o[9],  o[10], o[11]);
                    q[3] = make_float4(o[12], o[13], o[14], o[15]);
                    __syncwarp();
                    // warp-local transposed writeback of this warp's 32 rows
                    #pragma unroll
                    for (int ii = 0; ii < 16; ++ii) {
                        const int li  = rg * 16 + ii;         // 0..31
                        const int row = 4 * li + w32;
                        out[(pB + row) * TSTEPS + t0 + col] =
                            obuf[(w32 * 32 + li) * OBS + col];
                    }
                    __syncwarp();
                } else {
                    // last tile (w=10): scalar path, late release (1/16 tiles)
                    for (int j = 0; j < wv; ++j) {
                        const int si = slot * RW + s4 + j;
                        float a0 = fmaf(B[1 * ARRF + si], 0.10f, 0.05f);
                        float a1 = fmaf(B[2 * ARRF + si], 0.20f, 0.10f);
                        float b0 = B[3 * ARRF + si] * 0.05f;
                        float b1 = B[4 * ARRF + si] * 0.10f;
                        float gg = fmaf(B[5 * ARRF + si], 0.20f, 0.80f);
                        float zt = B[si] * SQRT_DT;
                        float base = fmaf(a1, fmaxf(s, 0.0f), a0);
                        s = fmaf(fmaf(b1, s, b0), DT_F, s) + __powf(base, gg) * zt;
                        obuf[slot * OBS + j] = s;
                    }
                    __syncwarp();
                    if (col < wv) {
                        #pragma unroll
                        for (int ii = 0; ii < 16; ++ii) {
                            const int li  = rg * 16 + ii;
                            const int row = 4 * li + w32;
                            out[(pB + row) * TSTEPS + t0 + col] =
                                obuf[(w32 * 32 + li) * OBS + col];
                        }
                    }
                    __syncwarp();
                    mbar_arrive(emp);
                }
                if (++cs == STAGES) { cs = 0; cph ^= 1; }
            }
        }
    }
}

extern "C" void kernel_launch(void* const* d_in, const int* in_sizes, int n_in,
                              void* d_out, int out_size)
{
    const float* Z   = (const float*)d_in[0];
    const float* Ua0 = (const float*)d_in[1];
    const float* Ua1 = (const float*)d_in[2];
    const float* Ub0 = (const float*)d_in[3];
    const float* Ub1 = (const float*)d_in[4];
    const float* Ug  = (const float*)d_in[5];
    float* out = (float*)d_out;

    const int N = in_sizes[0] / TSTEPS;             // 131072
    const int ngroups = (N + NROWS - 1) / NROWS;    // 1024
    const int blocks = ngroups < 148 ? ngroups : 148;

    // 64 + 3*15360 + 128*20 floats = 194,816 B
    const size_t smem = (size_t)(OBUF_OFF + NROWS * OBS) * sizeof(float);
    cudaFuncSetAttribute(gad_kernel, cudaFuncAttributeMaxDynamicSharedMemorySize, (int)smem);

    gad_kernel<<<blocks, 192, smem>>>(Z, Ua0, Ua1, Ub0, Ub1, Ug, out, ngroups);
}

// round 13
// speedup vs baseline: 1.5459x; 1.5459x over previous
#include <cuda_runtime.h>
#include <cstdint>

// path_generator_GAD  (N=131072 paths, T=251)
// s' = s + (b0+b1*s)*dt + (a0+a1*max(s,0))^g * Z*sqrt(dt)
//
// R13 = R11 (199us base: TW=16/RW=20/3-stage/dual-producer/persistent)
//  + elect-based empty arrives (count 128 -> 4; kills same-address ATOMS serialization)
//  + shortened serial chain: s' = fma(s, 1+b1*dt, b0*dt + pow*zt)
//  + unconditional full-tile writeback

#define TSTEPS  251
#define DT_F    0.004f
#define SQRT_DT 0.063245553203367586f
#define S0_F    100.0f
#define TW      16
#define RW      20                  // floats per row slot (16B multiple)
#define CHUNKS  5                   // RW/4 16B chunks per row
#define NROWS   128
#define NTILES  16                  // ceil(250/16)
#define STAGES  3
#define PLANES  64                  // producer lanes (2 warps)
#define ARRF    (NROWS * RW)        // 2560 floats per array tile
#define BUFF    (6 * ARRF)          // 15360 floats per stage
#define DATA_OFF 64                 // floats reserved for barriers

__device__ __forceinline__ void cp16(unsigned sa, const float* g) {
    asm volatile("cp.async.cg.shared.global [%0], [%1], 16;" :: "r"(sa), "l"(g));
}
__device__ __forceinline__ void cp4(unsigned sa, const float* g) {
    asm volatile("cp.async.ca.shared.global [%0], [%1], 4;" :: "r"(sa), "l"(g));
}
__device__ __forceinline__ void mbar_init(unsigned a, unsigned cnt) {
    asm volatile("mbarrier.init.shared.b64 [%0], %1;" :: "r"(a), "r"(cnt));
}
__device__ __forceinline__ void mbar_arrive(unsigned a) {
    asm volatile("mbarrier.arrive.shared.b64 _, [%0];" :: "r"(a) : "memory");
}
__device__ __forceinline__ void cp_arrive_noinc(unsigned a) {
    asm volatile("cp.async.mbarrier.arrive.noinc.shared.b64 [%0];" :: "r"(a) : "memory");
}
__device__ __forceinline__ unsigned elect_one() {
    unsigned pred;
    asm volatile(
        "{\n\t.reg .pred p;\n\t"
        "elect.sync _|p, 0xFFFFFFFF;\n\t"
        "selp.b32 %0, 1, 0, p;\n\t}" : "=r"(pred));
    return pred;
}
__device__ __forceinline__ void mbar_wait(unsigned a, unsigned ph) {
    unsigned done;
    asm volatile(
        "{\n\t.reg .pred p;\n\t"
        "mbarrier.try_wait.parity.acquire.cta.shared::cta.b64 p, [%1], %2;\n\t"
        "selp.b32 %0,1,0,p;\n\t}"
        : "=r"(done) : "r"(a), "r"(ph) : "memory");
    while (!done) {
        asm volatile(
            "{\n\t.reg .pred p;\n\t"
            "mbarrier.try_wait.parity.acquire.cta.shared::cta.b64 p, [%1], %2, 0x989680;\n\t"
            "selp.b32 %0,1,0,p;\n\t}"
            : "=r"(done) : "r"(a), "r"(ph) : "memory");
    }
}

template<int E>
__device__ __forceinline__ float elemf(const float4 (&v)[CHUNKS]) {
    constexpr int c = E >> 2;
    constexpr int m = E & 3;
    if constexpr (m == 0) return v[c].x;
    else if constexpr (m == 1) return v[c].y;
    else if constexpr (m == 2) return v[c].z;
    else return v[c].w;
}

template<int S>
__device__ __forceinline__ float run16(float s,
    const float4 (&vz)[CHUNKS], const float4 (&va0)[CHUNKS],
    const float4 (&va1)[CHUNKS], const float4 (&vb0)[CHUNKS],
    const float4 (&vb1)[CHUNKS], const float4 (&vg)[CHUNKS],
    float (&o)[TW])
{
    // chain-minimized step: s' = fma(s, 1 + b1*dt, b0*dt + pow*zt)
    //   off-chain ILP: coeff transforms, zt, m1 = 1+b1*dt, c0 = b0*dt
    //   on-chain:      max(s) -> fma(base) -> LG2 -> mul -> EX2 -> fma(zt*pow + c0 ... ) -> fma(s*m1 + t)
#define ONE(J)                                                         \
    {                                                                  \
        float a0 = fmaf(elemf<S+J>(va0), 0.10f, 0.05f);                \
        float a1 = fmaf(elemf<S+J>(va1), 0.20f, 0.10f);                \
        float c0 = elemf<S+J>(vb0) * (0.05f * DT_F);                   \
        float m1 = fmaf(elemf<S+J>(vb1), 0.10f * DT_F, 1.0f);         \
        float g  = fmaf(elemf<S+J>(vg), 0.20f, 0.80f);                 \
        float zt = elemf<S+J>(vz) * SQRT_DT;                           \
        float base = fmaf(a1, fmaxf(s, 0.0f), a0);                     \
        float t = fmaf(__powf(base, g), zt, c0);                       \
        s = fmaf(s, m1, t);                                            \
        o[J] = s;                                                      \
    }
    ONE(0)  ONE(1)  ONE(2)  ONE(3)  ONE(4)  ONE(5)  ONE(6)  ONE(7)
    ONE(8)  ONE(9)  ONE(10) ONE(11) ONE(12) ONE(13) ONE(14) ONE(15)
#undef ONE
    return s;
}

__global__ void __launch_bounds__(192, 1)
gad_kernel(const float* __restrict__ Z,
           const float* __restrict__ Ua0,
           const float* __restrict__ Ua1,
           const float* __restrict__ Ub0,
           const float* __restrict__ Ub1,
           const float* __restrict__ Ug,
           float* __restrict__ out, int ngroups)
{
    extern __shared__ float smem[];
    const int tid = threadIdx.x;
    const unsigned sb = (unsigned)__cvta_generic_to_shared(smem);
    if (tid == 0) {
        #pragma unroll
        for (int s = 0; s < STAGES; ++s) {
            mbar_init(sb + s * 16,     PLANES);  // full: 64 producer lanes
            mbar_init(sb + s * 16 + 8, 4);       // empty: 4 elected consumer lanes
        }
    }
    __syncthreads();

    float* data = smem + DATA_OFF;
    const unsigned dbase = sb + DATA_OFF * 4u;

    if (tid >= 128) {
        // ============ producer warps (2), persistent across groups ============
        const int lane = tid - 128;              // 0..63
        int ps = 0, pph = 1;
        for (int g = blockIdx.x; g < ngroups; g += gridDim.x) {
            const int pB = g * NROWS;
            for (int k = 0; k < NTILES; ++k) {
                const unsigned ful = sb + ps * 16;
                const unsigned emp = ful + 8;
                mbar_wait(emp, pph);
                const unsigned stage = dbase + (unsigned)(ps * BUFF) * 4u;
                const int t0 = 1 + k * TW;
                if (k < NTILES - 1) {
                    // 128 rows x 5 chunks x 6 arrays / 64 lanes = 60 cp16/lane
                    #pragma unroll
                    for (int i = 0; i < 10; ++i) {
                        const int c    = lane + PLANES * i;  // 0..639
                        const int row  = c / CHUNKS;
                        const int kk   = c - row * CHUNKS;   // 0..4
                        const int slot = ((row & 3) << 5) | (row >> 2);
                        const int slack = (t0 - row) & 3;
                        const int gi = (pB + row) * TSTEPS + t0 - slack + kk * 4;
                        const unsigned d = stage + (unsigned)(slot * RW + kk * 4) * 4u;
                        cp16(d + 0u * (ARRF * 4), Z   + gi);
                        cp16(d + 1u * (ARRF * 4), Ua0 + gi);
                        cp16(d + 2u * (ARRF * 4), Ua1 + gi);
                        cp16(d + 3u * (ARRF * 4), Ub0 + gi);
                        cp16(d + 4u * (ARRF * 4), Ub1 + gi);
                        cp16(d + 5u * (ARRF * 4), Ug  + gi);
                    }
                } else {
                    // last tile (w=10): exact 4B copies (no tail over-read)
                    const int w = TSTEPS - t0;               // 10
                    for (int idx = lane; idx < NROWS * w; idx += PLANES) {
                        const int row  = idx / w;
                        const int j    = idx - row * w;
                        const int slot = ((row & 3) << 5) | (row >> 2);
                        const int slack = (t0 - row) & 3;
                        const int gi = (pB + row) * TSTEPS + t0 + j;
                        const unsigned d = stage + (unsigned)(slot * RW + slack + j) * 4u;
                        cp4(d + 0u * (ARRF * 4), Z   + gi);
                        cp4(d + 1u * (ARRF * 4), Ua0 + gi);
                        cp4(d + 2u * (ARRF * 4), Ua1 + gi);
                        cp4(d + 3u * (ARRF * 4), Ub0 + gi);
                        cp4(d + 4u * (ARRF * 4), Ub1 + gi);
                        cp4(d + 5u * (ARRF * 4), Ug  + gi);
                    }
                }
                cp_arrive_noinc(ful);
                if (++ps == STAGES) { ps = 0; pph ^= 1; }
            }
        }
    } else {
        // ============ consumer warps (4), persistent across groups ============
        const int w32  = tid >> 5;          // warp id 0..3
        const int lane = tid & 31;
        const int r    = 4 * lane + w32;    // my path row (slack-uniform warps)
        const int slot = tid;               // smem slot (80B lane stride)
        const int col  = lane & 15;         // writeback role: 16 cols
        const int rg   = lane >> 4;         // 0/1
        int cs = 0, cph = 0;

        for (int g = blockIdx.x; g < ngroups; g += gridDim.x) {
            const int pB = g * NROWS;
            out[(pB + r) * TSTEPS] = S0_F;  // column 0 = S0
            float s = S0_F;

            for (int k = 0; k < NTILES; ++k) {
                const unsigned ful = sb + cs * 16;
                const unsigned emp = ful + 8;
                mbar_wait(ful, cph);

                float* B = data + cs * BUFF;
                const int t0 = 1 + k * TW;
                const int s4 = (t0 - w32) & 3;      // warp-uniform slack

                if (k < NTILES - 1) {
                    float4 vz[CHUNKS], va0[CHUNKS], va1[CHUNKS],
                           vb0[CHUNKS], vb1[CHUNKS], vg[CHUNKS];
                    const float4* p = reinterpret_cast<const float4*>(B) + slot * CHUNKS;
                    const int A4 = ARRF / 4;        // 640 float4 per array
                    #pragma unroll
                    for (int c = 0; c < CHUNKS; ++c) {
                        vz[c]  = p[0 * A4 + c];
                        va0[c] = p[1 * A4 + c];
                        va1[c] = p[2 * A4 + c];
                        vb0[c] = p[3 * A4 + c];
                        vb1[c] = p[4 * A4 + c];
                        vg[c]  = p[5 * A4 + c];
                    }
                    float o[TW];
                    switch (s4) {   // warp-uniform: exactly one case executes
                        case 0: s = run16<0>(s, vz, va0, va1, vb0, vb1, vg, o); break;
                        case 1: s = run16<1>(s, vz, va0, va1, vb0, vb1, vg, o); break;
                        case 2: s = run16<2>(s, vz, va0, va1, vb0, vb1, vg, o); break;
                        default: s = run16<3>(s, vz, va0, va1, vb0, vb1, vg, o); break;
                    }
                    float4* q = reinterpret_cast<float4*>(B) + slot * CHUNKS;
                    q[0] = make_float4(o[0],  o[1],  o[2],  o[3]);
                    q[1] = make_float4(o[4],  o[5],  o[6],  o[7]);
                    q[2] = make_float4(o[8],  o[9],  o[10], o[11]);
                    q[3] = make_float4(o[12], o[13], o[14], o[15]);

                    __syncwarp();
                    // warp-local transposed writeback (wv == 16 always here)
                    #pragma unroll
                    for (int ii = 0; ii < 16; ++ii) {
                        const int li  = rg * 16 + ii;         // 0..31
                        const int row = 4 * li + w32;
                        out[(pB + row) * TSTEPS + t0 + col] =
                            B[(w32 * 32 + li) * RW + col];
                    }
                    __syncwarp();
                } else {
                    // last tile (w=10): scalar path
                    const int wv = TSTEPS - t0;               // 10
                    for (int j = 0; j < wv; ++j) {
                        const int si = slot * RW + s4 + j;
                        float a0 = fmaf(B[1 * ARRF + si], 0.10f, 0.05f);
                        float a1 = fmaf(B[2 * ARRF + si], 0.20f, 0.10f);
                        float c0 = B[3 * ARRF + si] * (0.05f * DT_F);
                        float m1 = fmaf(B[4 * ARRF + si], 0.10f * DT_F, 1.0f);
                        float gg = fmaf(B[5 * ARRF + si], 0.20f, 0.80f);
                        float zt = B[si] * SQRT_DT;
                        float base = fmaf(a1, fmaxf(s, 0.0f), a0);
                        float t = fmaf(__powf(base, gg), zt, c0);
                        s = fmaf(s, m1, t);
                        B[slot * RW + j] = s;
                    }
                    __syncwarp();
                    if (col < wv) {
                        #pragma unroll
                        for (int ii = 0; ii < 16; ++ii) {
                            const int li  = rg * 16 + ii;
                            const int row = 4 * li + w32;
                            out[(pB + row) * TSTEPS + t0 + col] =
                                B[(w32 * 32 + li) * RW + col];
                        }
                    }
                    __syncwarp();
                }
                if (elect_one()) mbar_arrive(emp);   // one arrive per warp
                if (++cs == STAGES) { cs = 0; cph ^= 1; }
            }
        }
    }
}

extern "C" void kernel_launch(void* const* d_in, const int* in_sizes, int n_in,
                              void* d_out, int out_size)
{
    const float* Z   = (const float*)d_in[0];
    const float* Ua0 = (const float*)d_in[1];
    const float* Ua1 = (const float*)d_in[2];
    const float* Ub0 = (const float*)d_in[3];
    const float* Ub1 = (const float*)d_in[4];
    const float* Ug  = (const float*)d_in[5];
    float* out = (float*)d_out;

    const int N = in_sizes[0] / TSTEPS;             // 131072
    const int ngroups = (N + NROWS - 1) / NROWS;    // 1024
    const int blocks = ngroups < 148 ? ngroups : 148;

    const size_t smem = (size_t)(DATA_OFF + STAGES * BUFF) * sizeof(float); // 184576 B
    cudaFuncSetAttribute(gad_kernel, cudaFuncAttributeMaxDynamicSharedMemorySize, (int)smem);

    gad_kernel<<<blocks, 192, smem>>>(Z, Ua0, Ua1, Ub0, Ub1, Ug, out, ngroups);
}